// round 7
// baseline (speedup 1.0000x reference)
#include <cuda_runtime.h>
#include <cuda_bf16.h>
#include <math.h>
#include <stdint.h>

#define BATCH    32768
#define DIM      256
#define MAX_IT   40
#define NCTAS    512               // (BATCH/128) * (DIM/128)
#define EW_GRID  (BATCH*DIM/4/256)

// smem layout (bytes), K-chunk = 64
#define A_ST     144               // 72 bf16 per row (64 data + 8 pad)
#define W_ST     272               // 136 bf16 per row (128 data + 8 pad)
#define OFF_A0   0
#define OFF_A1   18432
#define OFF_W0   36864
#define OFF_W1   54272
#define SMEM_TOT 71680

// ---------------- device scratch ----------------
__device__ __nv_bfloat16 g_ya0[2][BATCH*DIM];   // y hi split, ping-pong
__device__ __nv_bfloat16 g_ya1[2][BATCH*DIM];   // y lo split
__device__ __nv_bfloat16 g_xa0[2][BATCH*DIM];   // x hi split
__device__ __nv_bfloat16 g_xa1[2][BATCH*DIM];   // x lo split
__device__ float g_b[BATCH*DIM];
__device__ float g_WU[DIM*DIM];                 // U^T for bias GEMM
__device__ __nv_bfloat16 g_w0[DIM*DIM];         // Weff hi split [k][n]
__device__ __nv_bfloat16 g_w1[DIM*DIM];         // Weff lo split
__device__ float g_partial[NCTAS*2];
__device__ int   g_active;

// ---------------- helpers ----------------
__device__ __forceinline__ uint32_t sptr(const void* p) {
    return (uint32_t)__cvta_generic_to_shared(p);
}
__device__ __forceinline__ uint32_t bpack(__nv_bfloat16 a, __nv_bfloat16 b) {
    uint16_t ua = *(uint16_t*)&a, ub = *(uint16_t*)&b;
    return (uint32_t)ua | ((uint32_t)ub << 16);
}
__device__ __forceinline__ void cpa16(uint32_t dst, const void* src) {
    asm volatile("cp.async.cg.shared.global [%0], [%1], 16;"
                 :: "r"(dst), "l"(src) : "memory");
}
__device__ __forceinline__ void cpa_commit() {
    asm volatile("cp.async.commit_group;" ::: "memory");
}
template<int N>
__device__ __forceinline__ void cpa_wait() {
    asm volatile("cp.async.wait_group %0;" :: "n"(N) : "memory");
}
__device__ __forceinline__ void ldm_x4(uint32_t* r, uint32_t addr) {
    asm volatile("ldmatrix.sync.aligned.m8n8.x4.shared.b16 {%0,%1,%2,%3}, [%4];"
                 : "=r"(r[0]), "=r"(r[1]), "=r"(r[2]), "=r"(r[3]) : "r"(addr));
}
__device__ __forceinline__ void ldm_x4t(uint32_t* r, uint32_t addr) {
    asm volatile("ldmatrix.sync.aligned.m8n8.x4.trans.shared.b16 {%0,%1,%2,%3}, [%4];"
                 : "=r"(r[0]), "=r"(r[1]), "=r"(r[2]), "=r"(r[3]) : "r"(addr));
}
__device__ __forceinline__ void mma_bf16(float* c, const uint32_t* a, const uint32_t* b) {
    asm volatile(
        "mma.sync.aligned.m16n8k16.row.col.f32.bf16.bf16.f32 "
        "{%0,%1,%2,%3}, {%4,%5,%6,%7}, {%8,%9}, {%0,%1,%2,%3};"
        : "+f"(c[0]), "+f"(c[1]), "+f"(c[2]), "+f"(c[3])
        : "r"(a[0]), "r"(a[1]), "r"(a[2]), "r"(a[3]), "r"(b[0]), "r"(b[1]));
}

// fp32x2 helpers for the bias GEMM
__device__ __forceinline__ unsigned long long pack2(float v) {
    unsigned long long r; unsigned u = __float_as_uint(v);
    asm("mov.b64 %0, {%1, %1};" : "=l"(r) : "r"(u));
    return r;
}
__device__ __forceinline__ void ffma2(unsigned long long& d,
                                      unsigned long long a, unsigned long long b) {
    asm("fma.rn.f32x2 %0, %1, %2, %0;" : "+l"(d) : "l"(a), "l"(b));
}
__device__ __forceinline__ float lo32(unsigned long long v) {
    return __uint_as_float((unsigned)(v & 0xffffffffull));
}
__device__ __forceinline__ float hi32(unsigned long long v) {
    return __uint_as_float((unsigned)(v >> 32));
}

// ---------------- prep: U^T, Weff -> bf16 splits ----------------
__global__ void prep_kernel(const float* __restrict__ U,
                            const float* __restrict__ A,
                            const float* __restrict__ B) {
    int i = blockIdx.x;    // k index (row of Weff)
    int j = threadIdx.x;   // n index (col)
    g_WU[i*DIM + j] = U[j*DIM + i];
    float s = 0.f;
#pragma unroll 8
    for (int p = 0; p < DIM; ++p)
        s = fmaf(A[p*DIM + i], A[p*DIM + j], s);
    float w = -s + B[j*DIM + i] - B[i*DIM + j];
    if (i == j) w += 0.8f;                    // (1-m), m=0.2
    __nv_bfloat16 h0 = __float2bfloat16(w);
    __nv_bfloat16 h1 = __float2bfloat16(w - __bfloat162float(h0));
    g_w0[i*DIM + j] = h0;
    g_w1[i*DIM + j] = h1;
}

__global__ void init_kernel() {
    int i = blockIdx.x * blockDim.x + threadIdx.x;
    uint2 z = make_uint2(0u, 0u);             // 4 bf16
    ((uint2*)g_ya0[0])[i] = z;
    ((uint2*)g_ya1[0])[i] = z;
    ((uint2*)g_xa0[0])[i] = z;
    ((uint2*)g_xa1[0])[i] = z;
    if (i == 0) g_active = 1;
}

// ---------------- bias GEMM (runs once, exact fp32): b = x @ U^T + ub ----------
__launch_bounds__(256, 2)
__global__ void bias_gemm(const float* __restrict__ Ap, const float* __restrict__ ub) {
    __shared__ float As[16][132];
    __shared__ float Bs[16][128];
    const int tid = threadIdx.x;
    const int tx  = tid & 15, ty = tid >> 4;
    const int m0  = blockIdx.y * 128, n0 = blockIdx.x * 128;
    const int ra = tid >> 2, ca = (tid & 3) << 2;
    const int rb = tid >> 5, cb = (tid & 31) << 2;
    unsigned long long acc[8][4];
#pragma unroll
    for (int i = 0; i < 8; ++i)
#pragma unroll
        for (int j = 0; j < 4; ++j) acc[i][j] = 0ull;
    for (int k0 = 0; k0 < DIM; k0 += 16) {
        float4 a0 = *(const float4*)(Ap + (m0 + ra     ) * DIM + k0 + ca);
        float4 a1 = *(const float4*)(Ap + (m0 + ra + 64) * DIM + k0 + ca);
        float4 b0 = *(const float4*)(g_WU + (k0 + rb    ) * DIM + n0 + cb);
        float4 b1 = *(const float4*)(g_WU + (k0 + rb + 8) * DIM + n0 + cb);
        __syncthreads();
        As[ca+0][ra] = a0.x;  As[ca+1][ra] = a0.y;
        As[ca+2][ra] = a0.z;  As[ca+3][ra] = a0.w;
        As[ca+0][ra+64] = a1.x;  As[ca+1][ra+64] = a1.y;
        As[ca+2][ra+64] = a1.z;  As[ca+3][ra+64] = a1.w;
        *(float4*)&Bs[rb  ][cb] = b0;
        *(float4*)&Bs[rb+8][cb] = b1;
        __syncthreads();
#pragma unroll
        for (int kk = 0; kk < 16; ++kk) {
            unsigned long long pb[4], pa[8];
#pragma unroll
            for (int j = 0; j < 4; ++j)
                pb[j] = *(const unsigned long long*)&Bs[kk][tx*2 + j*32];
#pragma unroll
            for (int i = 0; i < 8; ++i) pa[i] = pack2(As[kk][ty*8 + i]);
#pragma unroll
            for (int i = 0; i < 8; ++i)
#pragma unroll
                for (int j = 0; j < 4; ++j) ffma2(acc[i][j], pa[i], pb[j]);
        }
    }
    float2 u[4];
#pragma unroll
    for (int j = 0; j < 4; ++j) u[j] = *(const float2*)(ub + n0 + tx*2 + j*32);
#pragma unroll
    for (int i = 0; i < 8; ++i) {
        float* base = g_b + (m0 + ty*8 + i)*DIM + n0;
#pragma unroll
        for (int j = 0; j < 4; ++j) {
            float2 g;
            g.x = lo32(acc[i][j]) + u[j].x;
            g.y = hi32(acc[i][j]) + u[j].y;
            *(float2*)(base + tx*2 + j*32) = g;
        }
    }
}

// ---------------- iteration kernel: split-bf16 MMA, K-chunk=64 ----------------
// G[128,128] = a0@w0 + a1@w0 + a0@w1 (fp32 accum), fused epilogue:
//   fn = relu(G+b) -> out; err partials from (y, fn);
//   x' = relu(0.5*(y+G+b)); y' = x' + beta*(x'-x); x',y' stored as bf16 splits
__global__ void __launch_bounds__(256, 2)
iter_kernel(float beta, int par, float* __restrict__ outp) {
    if (g_active == 0) return;
    extern __shared__ __align__(16) unsigned char sm[];
    const uint32_t sb = sptr(sm);

    const int tid  = threadIdx.x;
    const int lane = tid & 31;
    const int wid  = tid >> 5;
    const int wm   = wid & 3;      // warp M index (32 rows each)
    const int wn   = wid >> 2;     // warp N index (64 cols each)
    const int m0   = blockIdx.y * 128;
    const int n0   = blockIdx.x * 128;

    const __nv_bfloat16* __restrict__ ya0 = g_ya0[par];
    const __nv_bfloat16* __restrict__ ya1 = g_ya1[par];

    float acc[2][8][4];
#pragma unroll
    for (int mi = 0; mi < 2; ++mi)
#pragma unroll
        for (int ni = 0; ni < 8; ++ni)
#pragma unroll
            for (int q = 0; q < 4; ++q) acc[mi][ni][q] = 0.f;

    // ldmatrix lane addresses (R5 fragment mapping, new strides)
    const uint32_t aoff = (uint32_t)((wm*32 + (lane & 15)) * A_ST + (lane >> 4) * 16);
    const uint32_t boff = (uint32_t)((((lane >> 3) & 1) * 8 + (lane & 7)) * W_ST
                                     + (wn*64 + (lane >> 4) * 8) * 2);

#pragma unroll 1
    for (int kc = 0; kc < 4; ++kc) {
        // --- fill stage: pure 16B copies via cp.async ---
#pragma unroll
        for (int p = 0; p < 4; ++p) {
            int idx = tid + p * 256;
            int r = idx >> 3, s = idx & 7;         // 128 rows x 8 segs
            uint32_t d = sb + r * A_ST + s * 16;
            size_t o = (size_t)(m0 + r) * DIM + kc*64 + s*8;
            cpa16(d + OFF_A0, ya0 + o);
            cpa16(d + OFF_A1, ya1 + o);
        }
#pragma unroll
        for (int p = 0; p < 4; ++p) {
            int idx = tid + p * 256;
            int r = idx >> 4, s = idx & 15;        // 64 rows x 16 segs
            uint32_t d = sb + r * W_ST + s * 16;
            size_t o = (size_t)(kc*64 + r) * DIM + n0 + s*8;
            cpa16(d + OFF_W0, g_w0 + o);
            cpa16(d + OFF_W1, g_w1 + o);
        }
        cpa_commit();
        cpa_wait<0>();
        __syncthreads();

#pragma unroll
        for (int kk2 = 0; kk2 < 4; ++kk2) {
            const uint32_t akb = (uint32_t)(kk2 * 32);           // 16 bf16 cols
            const uint32_t bkb = (uint32_t)(kk2 * 16 * W_ST);    // 16 k rows
            uint32_t a0f[2][4], a1f[2][4];
            ldm_x4(a0f[0], sb + OFF_A0 + aoff + akb);
            ldm_x4(a0f[1], sb + OFF_A0 + aoff + akb + 16*A_ST);
            ldm_x4(a1f[0], sb + OFF_A1 + aoff + akb);
            ldm_x4(a1f[1], sb + OFF_A1 + aoff + akb + 16*A_ST);
            uint32_t bf[8][2];
#pragma unroll
            for (int nb = 0; nb < 4; ++nb) {
                uint32_t r[4];
                ldm_x4t(r, sb + OFF_W0 + boff + bkb + nb*16*2);
                bf[nb*2  ][0] = r[0];  bf[nb*2  ][1] = r[1];
                bf[nb*2+1][0] = r[2];  bf[nb*2+1][1] = r[3];
            }
#pragma unroll
            for (int mi = 0; mi < 2; ++mi)
#pragma unroll
                for (int ni = 0; ni < 8; ++ni)
                    mma_bf16(acc[mi][ni], a0f[mi], bf[ni]);
#pragma unroll
            for (int mi = 0; mi < 2; ++mi)
#pragma unroll
                for (int ni = 0; ni < 8; ++ni)
                    mma_bf16(acc[mi][ni], a1f[mi], bf[ni]);
#pragma unroll
            for (int nb = 0; nb < 4; ++nb) {
                uint32_t r[4];
                ldm_x4t(r, sb + OFF_W1 + boff + bkb + nb*16*2);
                bf[nb*2  ][0] = r[0];  bf[nb*2  ][1] = r[1];
                bf[nb*2+1][0] = r[2];  bf[nb*2+1][1] = r[3];
            }
#pragma unroll
            for (int mi = 0; mi < 2; ++mi)
#pragma unroll
                for (int ni = 0; ni < 8; ++ni)
                    mma_bf16(acc[mi][ni], a0f[mi], bf[ni]);
        }
        __syncthreads();   // stage free for next chunk
    }

    // --- fused epilogue at fragment positions ---
    const __nv_bfloat16* __restrict__ xr0 = g_xa0[par];
    const __nv_bfloat16* __restrict__ xr1 = g_xa1[par];
    __nv_bfloat16* __restrict__ x0w = g_xa0[par ^ 1];
    __nv_bfloat16* __restrict__ x1w = g_xa1[par ^ 1];
    __nv_bfloat16* __restrict__ y0w = g_ya0[par ^ 1];
    __nv_bfloat16* __restrict__ y1w = g_ya1[par ^ 1];
    float sn = 0.f, sd = 0.f;
#pragma unroll
    for (int mi = 0; mi < 2; ++mi) {
#pragma unroll
        for (int h = 0; h < 2; ++h) {
            int row = m0 + wm*32 + mi*16 + (lane >> 2) + h*8;
#pragma unroll
            for (int ni = 0; ni < 8; ++ni) {
                int col = n0 + wn*64 + ni*8 + (lane & 3)*2;
                int gi = row * DIM + col;
                float g0 = acc[mi][ni][h*2], g1 = acc[mi][ni][h*2 + 1];
                float2 bv = *(const float2*)(g_b + gi);
                __nv_bfloat162 yh = *(const __nv_bfloat162*)(ya0 + gi);
                __nv_bfloat162 yl = *(const __nv_bfloat162*)(ya1 + gi);
                __nv_bfloat162 xh = *(const __nv_bfloat162*)(xr0 + gi);
                __nv_bfloat162 xl = *(const __nv_bfloat162*)(xr1 + gi);
                float yv0 = __bfloat162float(yh.x) + __bfloat162float(yl.x);
                float yv1 = __bfloat162float(yh.y) + __bfloat162float(yl.y);
                float xv0 = __bfloat162float(xh.x) + __bfloat162float(xl.x);
                float xv1 = __bfloat162float(xh.y) + __bfloat162float(xl.y);
                float2 fn;
                fn.x = fmaxf(g0 + bv.x, 0.f);
                fn.y = fmaxf(g1 + bv.y, 0.f);
                float d0 = yv0 - fn.x, d1 = yv1 - fn.y;
                sn = fmaf(d0, d0, sn);    sn = fmaf(d1, d1, sn);
                sd = fmaf(yv0, yv0, sd);  sd = fmaf(yv1, yv1, sd);
                float xn0 = fmaxf(0.5f*(yv0 + g0 + bv.x), 0.f);
                float xn1 = fmaxf(0.5f*(yv1 + g1 + bv.y), 0.f);
                float yn0 = xn0 + beta*(xn0 - xv0);
                float yn1 = xn1 + beta*(xn1 - xv1);
                *(float2*)(outp + gi) = fn;
                __nv_bfloat16 xh0 = __float2bfloat16(xn0);
                __nv_bfloat16 xh1 = __float2bfloat16(xn1);
                __nv_bfloat16 xl0 = __float2bfloat16(xn0 - __bfloat162float(xh0));
                __nv_bfloat16 xl1 = __float2bfloat16(xn1 - __bfloat162float(xh1));
                *(uint32_t*)(x0w + gi) = bpack(xh0, xh1);
                *(uint32_t*)(x1w + gi) = bpack(xl0, xl1);
                __nv_bfloat16 yh0 = __float2bfloat16(yn0);
                __nv_bfloat16 yh1 = __float2bfloat16(yn1);
                __nv_bfloat16 yl0 = __float2bfloat16(yn0 - __bfloat162float(yh0));
                __nv_bfloat16 yl1 = __float2bfloat16(yn1 - __bfloat162float(yh1));
                *(uint32_t*)(y0w + gi) = bpack(yh0, yh1);
                *(uint32_t*)(y1w + gi) = bpack(yl0, yl1);
            }
        }
    }

    // deterministic block reduction
    __syncthreads();
    float* red = (float*)sm;
    red[tid] = sn;  red[256 + tid] = sd;
    __syncthreads();
#pragma unroll
    for (int s = 128; s > 0; s >>= 1) {
        if (tid < s) { red[tid] += red[tid + s]; red[256 + tid] += red[256 + tid + s]; }
        __syncthreads();
    }
    if (tid == 0) {
        int bid = blockIdx.y * 2 + blockIdx.x;
        g_partial[bid*2    ] = red[0];
        g_partial[bid*2 + 1] = red[256];
    }
}

// ---------------- convergence check ----------------
__global__ void check_kernel() {
    if (g_active == 0) return;
    __shared__ float sn[256], sd[256];
    int t = threadIdx.x;
    float a = g_partial[2*t      ] + g_partial[2*(t + 256)    ];
    float b = g_partial[2*t + 1  ] + g_partial[2*(t + 256) + 1];
    sn[t] = a; sd[t] = b;
    __syncthreads();
#pragma unroll
    for (int s = 128; s > 0; s >>= 1) {
        if (t < s) { sn[t] += sn[t + s]; sd[t] += sd[t + s]; }
        __syncthreads();
    }
    if (t == 0) {
        float err = sqrtf(sn[0]) / (1e-6f + sqrtf(sd[0]));
        if (!(err > 1e-4f)) g_active = 0;
    }
}

// ---------------- launch ----------------
extern "C" void kernel_launch(void* const* d_in, const int* in_sizes, int n_in,
                              void* d_out, int out_size) {
    const float* x  = (const float*)d_in[0];
    const float* U  = (const float*)d_in[1];
    const float* ub = (const float*)d_in[2];
    const float* A  = (const float*)d_in[3];
    const float* B  = (const float*)d_in[4];
    (void)in_sizes; (void)n_in; (void)out_size;

    cudaFuncSetAttribute(iter_kernel,
                         cudaFuncAttributeMaxDynamicSharedMemorySize, SMEM_TOT);

    prep_kernel<<<DIM, DIM>>>(U, A, B);
    init_kernel<<<EW_GRID, 256>>>();

    dim3 bgrid(2, 256);
    bias_gemm<<<bgrid, 256>>>(x, ub);

    // kernel i: forward of body i + fn/err of body i-1 (gating validated R1/R2/R5)
    dim3 igrid(2, 256);
    float t = 1.0f;
    for (int i = 1; i <= MAX_IT + 1; ++i) {
        float tn   = 0.5f * (1.0f + sqrtf(1.0f + 4.0f * t * t));
        float beta = (t - 1.0f) / tn;
        iter_kernel<<<igrid, 256, SMEM_TOT>>>(beta, (i - 1) & 1, (float*)d_out);
        if (i <= MAX_IT) check_kernel<<<1, 256>>>();
        t = tn;
    }
}

// round 8
// speedup vs baseline: 1.1430x; 1.1430x over previous
#include <cuda_runtime.h>
#include <cuda_bf16.h>
#include <math.h>
#include <stdint.h>

#define BATCH    32768
#define DIM      256
#define MAX_IT   40
#define NCTAS    512               // grid (2, 256)
#define EW_GRID  (BATCH*DIM/4/256)
#define YF_ELEMS (2048*16*2*32)    // [mtile][kk16][half][lane] uint4
#define XS_ELEMS (BATCH*128)       // [row*128 + col/2] uint2

// ---------------- device scratch ----------------
__device__ uint4 g_yf[2][YF_ELEMS];     // y as A-fragments (hi,hi,lo,lo), ping-pong
__device__ uint2 g_xs[2][XS_ELEMS];     // x as interleaved bf16 splits, ping-pong
__device__ uint4 g_wf[16*32*32];        // W as B-fragments [kk][n8][lane]
__device__ float g_b[BATCH*DIM];
__device__ float g_WU[DIM*DIM];         // U^T for bias GEMM
__device__ __nv_bfloat16 g_w0[DIM*DIM]; // Weff hi split [k][n] (prep staging)
__device__ __nv_bfloat16 g_w1[DIM*DIM]; // Weff lo split
__device__ float g_partial[NCTAS*2];
__device__ int   g_ctr[MAX_IT+2];
__device__ int   g_active;

// ---------------- helpers ----------------
__device__ __forceinline__ uint32_t bpack(__nv_bfloat16 a, __nv_bfloat16 b) {
    uint16_t ua = *(uint16_t*)&a, ub = *(uint16_t*)&b;
    return (uint32_t)ua | ((uint32_t)ub << 16);
}
__device__ __forceinline__ float2 bunpack(uint32_t u) {
    __nv_bfloat162 h = *(__nv_bfloat162*)&u;
    return make_float2(__bfloat162float(h.x), __bfloat162float(h.y));
}
__device__ __forceinline__ uint32_t split_hi(float a, float b,
                                             float& ra, float& rb) {
    __nv_bfloat16 ha = __float2bfloat16(a), hb = __float2bfloat16(b);
    ra = a - __bfloat162float(ha);
    rb = b - __bfloat162float(hb);
    return bpack(ha, hb);
}
__device__ __forceinline__ uint32_t pack_lo(float ra, float rb) {
    return bpack(__float2bfloat16(ra), __float2bfloat16(rb));
}
__device__ __forceinline__ void mma_bf16(float* c, const uint32_t* a, const uint32_t* b) {
    asm volatile(
        "mma.sync.aligned.m16n8k16.row.col.f32.bf16.bf16.f32 "
        "{%0,%1,%2,%3}, {%4,%5,%6,%7}, {%8,%9}, {%0,%1,%2,%3};"
        : "+f"(c[0]), "+f"(c[1]), "+f"(c[2]), "+f"(c[3])
        : "r"(a[0]), "r"(a[1]), "r"(a[2]), "r"(a[3]), "r"(b[0]), "r"(b[1]));
}

// fp32x2 helpers for the bias GEMM
__device__ __forceinline__ unsigned long long pack2(float v) {
    unsigned long long r; unsigned u = __float_as_uint(v);
    asm("mov.b64 %0, {%1, %1};" : "=l"(r) : "r"(u));
    return r;
}
__device__ __forceinline__ void ffma2(unsigned long long& d,
                                      unsigned long long a, unsigned long long b) {
    asm("fma.rn.f32x2 %0, %1, %2, %0;" : "+l"(d) : "l"(a), "l"(b));
}
__device__ __forceinline__ float lo32(unsigned long long v) {
    return __uint_as_float((unsigned)(v & 0xffffffffull));
}
__device__ __forceinline__ float hi32(unsigned long long v) {
    return __uint_as_float((unsigned)(v >> 32));
}

// ---------------- prep: U^T, Weff -> bf16 splits (row-major staging) ----------
__global__ void prep_kernel(const float* __restrict__ U,
                            const float* __restrict__ A,
                            const float* __restrict__ B) {
    int i = blockIdx.x;    // k
    int j = threadIdx.x;   // n
    g_WU[i*DIM + j] = U[j*DIM + i];
    float s = 0.f;
#pragma unroll 8
    for (int p = 0; p < DIM; ++p)
        s = fmaf(A[p*DIM + i], A[p*DIM + j], s);
    float w = -s + B[j*DIM + i] - B[i*DIM + j];
    if (i == j) w += 0.8f;                    // (1-m), m=0.2
    __nv_bfloat16 h0 = __float2bfloat16(w);
    __nv_bfloat16 h1 = __float2bfloat16(w - __bfloat162float(h0));
    g_w0[i*DIM + j] = h0;
    g_w1[i*DIM + j] = h1;
}

// ---------------- prep2: pack W into B-fragment order ----------------
// B frag m16n8k16 (col): lane T: b0 = {B[k0][n], B[k0+1][n]}, b1 = {B[k0+8][n], B[k0+9][n]}
// with k0 = kk*16 + 2*(T%4), n = n8*8 + T/4.
__global__ void prep2_kernel() {
    int kk = blockIdx.x, n8 = blockIdx.y, lane = threadIdx.x;
    int k0 = kk*16 + 2*(lane & 3);
    int n  = n8*8 + (lane >> 2);
    uint4 u;
    u.x = bpack(g_w0[(k0    )*DIM + n], g_w0[(k0+1)*DIM + n]);
    u.y = bpack(g_w0[(k0 + 8)*DIM + n], g_w0[(k0+9)*DIM + n]);
    u.z = bpack(g_w1[(k0    )*DIM + n], g_w1[(k0+1)*DIM + n]);
    u.w = bpack(g_w1[(k0 + 8)*DIM + n], g_w1[(k0+9)*DIM + n]);
    g_wf[(kk*32 + n8)*32 + lane] = u;
}

// ---------------- init: zero y frags, x splits, counters ----------------
__global__ void init_kernel() {
    int i = blockIdx.x * blockDim.x + threadIdx.x;   // 0..2M-1
    g_yf[0][i] = make_uint4(0u, 0u, 0u, 0u);
    g_xs[0][2*i    ] = make_uint2(0u, 0u);
    g_xs[0][2*i + 1] = make_uint2(0u, 0u);
    if (i == 0) g_active = 1;
    if (i <= MAX_IT + 1) g_ctr[i] = 0;
}

// ---------------- bias GEMM (runs once, exact fp32): b = x @ U^T + ub ----------
__launch_bounds__(256, 2)
__global__ void bias_gemm(const float* __restrict__ Ap, const float* __restrict__ ub) {
    __shared__ float As[16][132];
    __shared__ float Bs[16][128];
    const int tid = threadIdx.x;
    const int tx  = tid & 15, ty = tid >> 4;
    const int m0  = blockIdx.y * 128, n0 = blockIdx.x * 128;
    const int ra = tid >> 2, ca = (tid & 3) << 2;
    const int rb = tid >> 5, cb = (tid & 31) << 2;
    unsigned long long acc[8][4];
#pragma unroll
    for (int i = 0; i < 8; ++i)
#pragma unroll
        for (int j = 0; j < 4; ++j) acc[i][j] = 0ull;
    for (int k0 = 0; k0 < DIM; k0 += 16) {
        float4 a0 = *(const float4*)(Ap + (m0 + ra     ) * DIM + k0 + ca);
        float4 a1 = *(const float4*)(Ap + (m0 + ra + 64) * DIM + k0 + ca);
        float4 b0 = *(const float4*)(g_WU + (k0 + rb    ) * DIM + n0 + cb);
        float4 b1 = *(const float4*)(g_WU + (k0 + rb + 8) * DIM + n0 + cb);
        __syncthreads();
        As[ca+0][ra] = a0.x;  As[ca+1][ra] = a0.y;
        As[ca+2][ra] = a0.z;  As[ca+3][ra] = a0.w;
        As[ca+0][ra+64] = a1.x;  As[ca+1][ra+64] = a1.y;
        As[ca+2][ra+64] = a1.z;  As[ca+3][ra+64] = a1.w;
        *(float4*)&Bs[rb  ][cb] = b0;
        *(float4*)&Bs[rb+8][cb] = b1;
        __syncthreads();
#pragma unroll
        for (int kk = 0; kk < 16; ++kk) {
            unsigned long long pb[4], pa[8];
#pragma unroll
            for (int j = 0; j < 4; ++j)
                pb[j] = *(const unsigned long long*)&Bs[kk][tx*2 + j*32];
#pragma unroll
            for (int i = 0; i < 8; ++i) pa[i] = pack2(As[kk][ty*8 + i]);
#pragma unroll
            for (int i = 0; i < 8; ++i)
#pragma unroll
                for (int j = 0; j < 4; ++j) ffma2(acc[i][j], pa[i], pb[j]);
        }
    }
    float2 u[4];
#pragma unroll
    for (int j = 0; j < 4; ++j) u[j] = *(const float2*)(ub + n0 + tx*2 + j*32);
#pragma unroll
    for (int i = 0; i < 8; ++i) {
        float* base = g_b + (m0 + ty*8 + i)*DIM + n0;
#pragma unroll
        for (int j = 0; j < 4; ++j) {
            float2 g;
            g.x = lo32(acc[i][j]) + u[j].x;
            g.y = hi32(acc[i][j]) + u[j].y;
            *(float2*)(base + tx*2 + j*32) = g;
        }
    }
}

// ---------------- iteration kernel: fragment-resident split-bf16 MMA ----------
// G = a0@w0 + a1@w0 + a0@w1; fused epilogue + merged convergence check.
__global__ void __launch_bounds__(256, 2)
iter_kernel(float beta, int par, int it, float* __restrict__ outp) {
    if (g_active == 0) return;
    const int tid  = threadIdx.x;
    const int lane = tid & 31;
    const int wid  = tid >> 5;
    const int wm   = wid & 3;          // warp M index (32 rows)
    const int wn   = wid >> 2;         // warp N index (64 cols)
    const int mb   = blockIdx.y;       // 0..255
    const int nb   = blockIdx.x;       // 0..1

    const uint4* __restrict__ yf = g_yf[par];

    float acc[2][8][4];
#pragma unroll
    for (int mi = 0; mi < 2; ++mi)
#pragma unroll
        for (int ni = 0; ni < 8; ++ni)
#pragma unroll
            for (int q = 0; q < 4; ++q) acc[mi][ni][q] = 0.f;

    const int mt0 = mb*8 + wm*2;                 // mtile for mi=0
    const int wfbase = (nb*16 + wn*8)*32 + lane; // + kk*1024 + nj*32

#pragma unroll
    for (int kk = 0; kk < 16; ++kk) {
        uint32_t ah[2][4], al[2][4];
#pragma unroll
        for (int mi = 0; mi < 2; ++mi) {
            int base = (((mt0 + mi)*16 + kk)*2)*32 + lane;
            uint4 u0 = yf[base];
            uint4 u1 = yf[base + 32];
            ah[mi][0] = u0.x; ah[mi][1] = u0.y; ah[mi][2] = u1.x; ah[mi][3] = u1.y;
            al[mi][0] = u0.z; al[mi][1] = u0.w; al[mi][2] = u1.z; al[mi][3] = u1.w;
        }
#pragma unroll
        for (int nh = 0; nh < 2; ++nh) {
            uint32_t bh[4][2], bl[4][2];
#pragma unroll
            for (int nj = 0; nj < 4; ++nj) {
                uint4 u = g_wf[kk*1024 + wfbase + (nh*4 + nj)*32];
                bh[nj][0] = u.x; bh[nj][1] = u.y;
                bl[nj][0] = u.z; bl[nj][1] = u.w;
            }
#pragma unroll
            for (int mi = 0; mi < 2; ++mi)
#pragma unroll
                for (int nj = 0; nj < 4; ++nj) {
                    float* c = acc[mi][nh*4 + nj];
                    mma_bf16(c, ah[mi], bh[nj]);
                    mma_bf16(c, al[mi], bh[nj]);
                    mma_bf16(c, ah[mi], bl[nj]);
                }
        }
    }

    // ---- fused epilogue ----
    const uint2* __restrict__ xs = g_xs[par];
    uint2* __restrict__ xsw = g_xs[par ^ 1];
    uint4* __restrict__ yfw = g_yf[par ^ 1];
    const int t2 = lane & 3, g = lane >> 2;
    float sn = 0.f, sd = 0.f;

#pragma unroll
    for (int mi = 0; mi < 2; ++mi) {
        int row0 = mb*128 + wm*32 + mi*16 + g;   // h=0 row (global)
#pragma unroll
        for (int ni = 0; ni < 8; ++ni) {
            int k8  = nb*16 + wn*8 + ni;
            int col = nb*128 + wn*64 + ni*8 + t2*2;
            int yidx = (((mt0 + mi)*16 + (k8 >> 1))*2 + (k8 & 1))*32 + lane;
            uint4 yu = yf[yidx];
            float2 a0h = bunpack(yu.x), a1h = bunpack(yu.y);
            float2 a0l = bunpack(yu.z), a1l = bunpack(yu.w);
            float y00 = a0h.x + a0l.x, y01 = a0h.y + a0l.y;   // row0, col/col+1
            float y10 = a1h.x + a1l.x, y11 = a1h.y + a1l.y;   // row0+8
            float g00 = acc[mi][ni][0], g01 = acc[mi][ni][1];
            float g10 = acc[mi][ni][2], g11 = acc[mi][ni][3];
            int gi0 = row0*DIM + col, gi1 = gi0 + 8*DIM;
            float2 b0 = *(const float2*)(g_b + gi0);
            float2 b1 = *(const float2*)(g_b + gi1);
            // fn = relu(G+b) -> out; err partials
            float fn00 = fmaxf(g00 + b0.x, 0.f), fn01 = fmaxf(g01 + b0.y, 0.f);
            float fn10 = fmaxf(g10 + b1.x, 0.f), fn11 = fmaxf(g11 + b1.y, 0.f);
            float d0 = y00-fn00, d1 = y01-fn01, d2 = y10-fn10, d3 = y11-fn11;
            sn = fmaf(d0,d0,sn); sn = fmaf(d1,d1,sn);
            sn = fmaf(d2,d2,sn); sn = fmaf(d3,d3,sn);
            sd = fmaf(y00,y00,sd); sd = fmaf(y01,y01,sd);
            sd = fmaf(y10,y10,sd); sd = fmaf(y11,y11,sd);
            *(float2*)(outp + gi0) = make_float2(fn00, fn01);
            *(float2*)(outp + gi1) = make_float2(fn10, fn11);
            // x' = relu(0.5*(y+G+b)); y' = x' + beta*(x'-x)
            float xn00 = fmaxf(0.5f*(y00 + g00 + b0.x), 0.f);
            float xn01 = fmaxf(0.5f*(y01 + g01 + b0.y), 0.f);
            float xn10 = fmaxf(0.5f*(y10 + g10 + b1.x), 0.f);
            float xn11 = fmaxf(0.5f*(y11 + g11 + b1.y), 0.f);
            int xi0 = gi0 >> 1, xi1 = gi1 >> 1;
            uint2 xu0 = xs[xi0], xu1 = xs[xi1];
            float2 x0h = bunpack(xu0.x), x0l = bunpack(xu0.y);
            float2 x1h = bunpack(xu1.x), x1l = bunpack(xu1.y);
            float yn00 = xn00 + beta*(xn00 - (x0h.x + x0l.x));
            float yn01 = xn01 + beta*(xn01 - (x0h.y + x0l.y));
            float yn10 = xn10 + beta*(xn10 - (x1h.x + x1l.x));
            float yn11 = xn11 + beta*(xn11 - (x1h.y + x1l.y));
            // store x' as interleaved splits
            float r0, r1, r2, r3;
            uint32_t xh0 = split_hi(xn00, xn01, r0, r1);
            uint2 xo0 = make_uint2(xh0, pack_lo(r0, r1));
            uint32_t xh1 = split_hi(xn10, xn11, r2, r3);
            uint2 xo1 = make_uint2(xh1, pack_lo(r2, r3));
            xsw[xi0] = xo0;  xsw[xi1] = xo1;
            // store y' as A-fragment (a0hi, a1hi, a0lo, a1lo)
            uint32_t yh0 = split_hi(yn00, yn01, r0, r1);
            uint32_t yh1 = split_hi(yn10, yn11, r2, r3);
            yfw[yidx] = make_uint4(yh0, yh1, pack_lo(r0, r1), pack_lo(r2, r3));
        }
    }

    // ---- deterministic block reduction ----
    __shared__ float red[512];
    red[tid] = sn;  red[256 + tid] = sd;
    __syncthreads();
#pragma unroll
    for (int s = 128; s > 0; s >>= 1) {
        if (tid < s) { red[tid] += red[tid + s]; red[256 + tid] += red[256 + tid + s]; }
        __syncthreads();
    }
    const int cta = mb*2 + nb;
    if (tid == 0) {
        g_partial[cta*2    ] = red[0];
        g_partial[cta*2 + 1] = red[256];
    }

    // ---- merged convergence check: last CTA reduces and gates ----
    __shared__ int islast;
    __threadfence();
    if (tid == 0) islast = (atomicAdd(&g_ctr[it], 1) == NCTAS - 1);
    __syncthreads();
    if (islast) {
        float a = g_partial[2*tid      ] + g_partial[2*(tid + 256)    ];
        float b = g_partial[2*tid + 1  ] + g_partial[2*(tid + 256) + 1];
        red[tid] = a; red[256 + tid] = b;
        __syncthreads();
#pragma unroll
        for (int s = 128; s > 0; s >>= 1) {
            if (tid < s) { red[tid] += red[tid + s]; red[256 + tid] += red[256 + tid + s]; }
            __syncthreads();
        }
        if (tid == 0) {
            float err = sqrtf(red[0]) / (1e-6f + sqrtf(red[256]));
            if (!(err > 1e-4f)) g_active = 0;
        }
    }
}

// ---------------- launch ----------------
extern "C" void kernel_launch(void* const* d_in, const int* in_sizes, int n_in,
                              void* d_out, int out_size) {
    const float* x  = (const float*)d_in[0];
    const float* U  = (const float*)d_in[1];
    const float* ub = (const float*)d_in[2];
    const float* A  = (const float*)d_in[3];
    const float* B  = (const float*)d_in[4];
    (void)in_sizes; (void)n_in; (void)out_size;

    prep_kernel<<<DIM, DIM>>>(U, A, B);
    dim3 p2grid(16, 32);
    prep2_kernel<<<p2grid, 32>>>();
    init_kernel<<<YF_ELEMS/256, 256>>>();

    dim3 bgrid(2, 256);
    bias_gemm<<<bgrid, 256>>>(x, ub);

    // kernel i: forward of body i + fn/err of body i-1 (gating validated R1/R2/R5)
    dim3 igrid(2, 256);
    float t = 1.0f;
    for (int i = 1; i <= MAX_IT + 1; ++i) {
        float tn   = 0.5f * (1.0f + sqrtf(1.0f + 4.0f * t * t));
        float beta = (t - 1.0f) / tn;
        iter_kernel<<<igrid, 256>>>(beta, (i - 1) & 1, i - 1, (float*)d_out);
        t = tn;
    }
}

// round 10
// speedup vs baseline: 1.1951x; 1.0456x over previous
#include <cuda_runtime.h>
#include <cuda_bf16.h>
#include <math.h>
#include <stdint.h>

#define BATCH    32768
#define DIM      256
#define MAX_IT   40
#define NCTAS    1024              // grid (4, 256)
#define EW_GRID  (BATCH*DIM/4/256)
#define YF_ELEMS (2048*16*2*32)    // [mtile][kk16][half][lane] uint4
#define XS_ELEMS (BATCH*128)       // [row*128 + col/2] uint2
#define WS_BYTES 65536             // 4096 uint4: [kk][n8l][lane]

// ---------------- device scratch ----------------
__device__ uint4 g_yf[2][YF_ELEMS];     // y as A-fragments (hi,hi,lo,lo), ping-pong
__device__ uint2 g_xs[2][XS_ELEMS];     // x as interleaved bf16 splits, ping-pong
__device__ uint4 g_wf[16*32*32];        // W as B-fragments [kk][n8][lane]
__device__ float g_b[BATCH*DIM];
__device__ float g_WU[DIM*DIM];         // U^T for bias GEMM
__device__ __nv_bfloat16 g_w0[DIM*DIM]; // Weff hi split [k][n] (prep staging)
__device__ __nv_bfloat16 g_w1[DIM*DIM]; // Weff lo split
__device__ float g_partial[NCTAS*2];
__device__ int   g_ctr[MAX_IT+2];
__device__ int   g_active;

// ---------------- helpers ----------------
__device__ __forceinline__ uint32_t bpack(__nv_bfloat16 a, __nv_bfloat16 b) {
    uint16_t ua = *(uint16_t*)&a, ub = *(uint16_t*)&b;
    return (uint32_t)ua | ((uint32_t)ub << 16);
}
__device__ __forceinline__ float2 bunpack(uint32_t u) {
    __nv_bfloat162 h = *(__nv_bfloat162*)&u;
    return make_float2(__bfloat162float(h.x), __bfloat162float(h.y));
}
__device__ __forceinline__ uint32_t split_hi(float a, float b,
                                             float& ra, float& rb) {
    __nv_bfloat16 ha = __float2bfloat16(a), hb = __float2bfloat16(b);
    ra = a - __bfloat162float(ha);
    rb = b - __bfloat162float(hb);
    return bpack(ha, hb);
}
__device__ __forceinline__ uint32_t pack_lo(float ra, float rb) {
    return bpack(__float2bfloat16(ra), __float2bfloat16(rb));
}
__device__ __forceinline__ void mma_bf16(float* c, const uint32_t* a, const uint32_t* b) {
    asm volatile(
        "mma.sync.aligned.m16n8k16.row.col.f32.bf16.bf16.f32 "
        "{%0,%1,%2,%3}, {%4,%5,%6,%7}, {%8,%9}, {%0,%1,%2,%3};"
        : "+f"(c[0]), "+f"(c[1]), "+f"(c[2]), "+f"(c[3])
        : "r"(a[0]), "r"(a[1]), "r"(a[2]), "r"(a[3]), "r"(b[0]), "r"(b[1]));
}

// fp32x2 helpers for the bias GEMM
__device__ __forceinline__ unsigned long long pack2(float v) {
    unsigned long long r; unsigned u = __float_as_uint(v);
    asm("mov.b64 %0, {%1, %1};" : "=l"(r) : "r"(u));
    return r;
}
__device__ __forceinline__ void ffma2(unsigned long long& d,
                                      unsigned long long a, unsigned long long b) {
    asm("fma.rn.f32x2 %0, %1, %2, %0;" : "+l"(d) : "l"(a), "l"(b));
}
__device__ __forceinline__ float lo32(unsigned long long v) {
    return __uint_as_float((unsigned)(v & 0xffffffffull));
}
__device__ __forceinline__ float hi32(unsigned long long v) {
    return __uint_as_float((unsigned)(v >> 32));
}

// ---------------- prep: U^T, Weff -> bf16 splits (row-major staging) ----------
__global__ void prep_kernel(const float* __restrict__ U,
                            const float* __restrict__ A,
                            const float* __restrict__ B) {
    int i = blockIdx.x;    // k
    int j = threadIdx.x;   // n
    g_WU[i*DIM + j] = U[j*DIM + i];
    float s = 0.f;
#pragma unroll 8
    for (int p = 0; p < DIM; ++p)
        s = fmaf(A[p*DIM + i], A[p*DIM + j], s);
    float w = -s + B[j*DIM + i] - B[i*DIM + j];
    if (i == j) w += 0.8f;                    // (1-m), m=0.2
    __nv_bfloat16 h0 = __float2bfloat16(w);
    __nv_bfloat16 h1 = __float2bfloat16(w - __bfloat162float(h0));
    g_w0[i*DIM + j] = h0;
    g_w1[i*DIM + j] = h1;
}

// ---------------- prep2: pack W into B-fragment order ----------------
// B frag m16n8k16 (col): lane T: b0={B[k0][n],B[k0+1][n]}, b1={B[k0+8][n],B[k0+9][n]}
// with k0 = kk*16 + 2*(T%4), n = n8*8 + T/4.
__global__ void prep2_kernel() {
    int kk = blockIdx.x, n8 = blockIdx.y, lane = threadIdx.x;
    int k0 = kk*16 + 2*(lane & 3);
    int n  = n8*8 + (lane >> 2);
    uint4 u;
    u.x = bpack(g_w0[(k0    )*DIM + n], g_w0[(k0+1)*DIM + n]);
    u.y = bpack(g_w0[(k0 + 8)*DIM + n], g_w0[(k0+9)*DIM + n]);
    u.z = bpack(g_w1[(k0    )*DIM + n], g_w1[(k0+1)*DIM + n]);
    u.w = bpack(g_w1[(k0 + 8)*DIM + n], g_w1[(k0+9)*DIM + n]);
    g_wf[(kk*32 + n8)*32 + lane] = u;
}

// ---------------- init: zero y frags, x splits, counters ----------------
__global__ void init_kernel() {
    int i = blockIdx.x * blockDim.x + threadIdx.x;   // 0..2M-1
    g_yf[0][i] = make_uint4(0u, 0u, 0u, 0u);
    g_xs[0][2*i    ] = make_uint2(0u, 0u);
    g_xs[0][2*i + 1] = make_uint2(0u, 0u);
    if (i == 0) g_active = 1;
    if (i <= MAX_IT + 1) g_ctr[i] = 0;
}

// ---------------- bias GEMM (runs once, exact fp32): b = x @ U^T + ub ----------
__launch_bounds__(256, 2)
__global__ void bias_gemm(const float* __restrict__ Ap, const float* __restrict__ ub) {
    __shared__ float As[16][132];
    __shared__ float Bs[16][128];
    const int tid = threadIdx.x;
    const int tx  = tid & 15, ty = tid >> 4;
    const int m0  = blockIdx.y * 128, n0 = blockIdx.x * 128;
    const int ra = tid >> 2, ca = (tid & 3) << 2;
    const int rb = tid >> 5, cb = (tid & 31) << 2;
    unsigned long long acc[8][4];
#pragma unroll
    for (int i = 0; i < 8; ++i)
#pragma unroll
        for (int j = 0; j < 4; ++j) acc[i][j] = 0ull;
    for (int k0 = 0; k0 < DIM; k0 += 16) {
        float4 a0 = *(const float4*)(Ap + (m0 + ra     ) * DIM + k0 + ca);
        float4 a1 = *(const float4*)(Ap + (m0 + ra + 64) * DIM + k0 + ca);
        float4 b0 = *(const float4*)(g_WU + (k0 + rb    ) * DIM + n0 + cb);
        float4 b1 = *(const float4*)(g_WU + (k0 + rb + 8) * DIM + n0 + cb);
        __syncthreads();
        As[ca+0][ra] = a0.x;  As[ca+1][ra] = a0.y;
        As[ca+2][ra] = a0.z;  As[ca+3][ra] = a0.w;
        As[ca+0][ra+64] = a1.x;  As[ca+1][ra+64] = a1.y;
        As[ca+2][ra+64] = a1.z;  As[ca+3][ra+64] = a1.w;
        *(float4*)&Bs[rb  ][cb] = b0;
        *(float4*)&Bs[rb+8][cb] = b1;
        __syncthreads();
#pragma unroll
        for (int kk = 0; kk < 16; ++kk) {
            unsigned long long pb[4], pa[8];
#pragma unroll
            for (int j = 0; j < 4; ++j)
                pb[j] = *(const unsigned long long*)&Bs[kk][tx*2 + j*32];
#pragma unroll
            for (int i = 0; i < 8; ++i) pa[i] = pack2(As[kk][ty*8 + i]);
#pragma unroll
            for (int i = 0; i < 8; ++i)
#pragma unroll
                for (int j = 0; j < 4; ++j) ffma2(acc[i][j], pa[i], pb[j]);
        }
    }
    float2 u[4];
#pragma unroll
    for (int j = 0; j < 4; ++j) u[j] = *(const float2*)(ub + n0 + tx*2 + j*32);
#pragma unroll
    for (int i = 0; i < 8; ++i) {
        float* base = g_b + (m0 + ty*8 + i)*DIM + n0;
#pragma unroll
        for (int j = 0; j < 4; ++j) {
            float2 g;
            g.x = lo32(acc[i][j]) + u[j].x;
            g.y = hi32(acc[i][j]) + u[j].y;
            *(float2*)(base + tx*2 + j*32) = g;
        }
    }
}

// ---------------- iteration kernel: smem-W, fragment-y, 24 warps/SM ----------
// CTA tile 128M x 64N; 8 warps (4 M x 2 N), warp tile 32x32.
// G = a0@w0 + a1@w0 + a0@w1; fused epilogue + merged last-CTA check.
__global__ void __launch_bounds__(256, 3)
iter_kernel(float beta, int par, int it, float* __restrict__ outp) {
    if (g_active == 0) return;
    extern __shared__ __align__(16) uint4 ws[];   // [kk][n8l][lane] = 4096 uint4
    const int tid  = threadIdx.x;
    const int lane = tid & 31;
    const int wid  = tid >> 5;
    const int wm   = wid & 3;          // M slice (32 rows)
    const int wn   = wid >> 2;         // N slice (32 cols)
    const int mb   = blockIdx.y;       // 0..255
    const int nb   = blockIdx.x;       // 0..3

    // ---- stage this CTA's W-fragment slice (64 cols) into smem ----
#pragma unroll
    for (int j = 0; j < 16; ++j) {
        int linear = j*256 + tid;              // (kk*8 + n8l)*32 + lane
        int l  = linear & 31;
        int r  = linear >> 5;                  // 0..127
        int kk = r >> 3, n8l = r & 7;
        ws[linear] = g_wf[kk*1024 + (nb*8 + n8l)*32 + l];
    }
    __syncthreads();

    const uint4* __restrict__ yf = g_yf[par];

    float acc[2][4][4];
#pragma unroll
    for (int mi = 0; mi < 2; ++mi)
#pragma unroll
        for (int ni = 0; ni < 4; ++ni)
#pragma unroll
            for (int q = 0; q < 4; ++q) acc[mi][ni][q] = 0.f;

    const int mt0 = mb*8 + wm*2;

#pragma unroll
    for (int kk = 0; kk < 16; ++kk) {
        uint32_t ah[2][4], al[2][4];
#pragma unroll
        for (int mi = 0; mi < 2; ++mi) {
            int base = (((mt0 + mi)*16 + kk)*2)*32 + lane;
            uint4 u0 = yf[base];
            uint4 u1 = yf[base + 32];
            ah[mi][0] = u0.x; ah[mi][1] = u0.y; ah[mi][2] = u1.x; ah[mi][3] = u1.y;
            al[mi][0] = u0.z; al[mi][1] = u0.w; al[mi][2] = u1.z; al[mi][3] = u1.w;
        }
#pragma unroll
        for (int ni = 0; ni < 4; ++ni) {
            uint4 u = ws[(kk*8 + wn*4 + ni)*32 + lane];
            uint32_t bh[2] = {u.x, u.y};
            uint32_t bl[2] = {u.z, u.w};
#pragma unroll
            for (int mi = 0; mi < 2; ++mi) {
                float* c = acc[mi][ni];
                mma_bf16(c, ah[mi], bh);
                mma_bf16(c, al[mi], bh);
                mma_bf16(c, ah[mi], bl);
            }
        }
    }

    // ---- fused epilogue ----
    const uint2* __restrict__ xs = g_xs[par];
    uint2* __restrict__ xsw = g_xs[par ^ 1];
    uint4* __restrict__ yfw = g_yf[par ^ 1];
    const int t2 = lane & 3, g = lane >> 2;
    float sn = 0.f, sd = 0.f;

#pragma unroll
    for (int mi = 0; mi < 2; ++mi) {
        int row0 = mb*128 + wm*32 + mi*16 + g;
#pragma unroll
        for (int ni = 0; ni < 4; ++ni) {
            int k8  = nb*8 + wn*4 + ni;
            int col = k8*8 + t2*2;
            int yidx = (((mt0 + mi)*16 + (k8 >> 1))*2 + (k8 & 1))*32 + lane;
            uint4 yu = yf[yidx];
            float2 a0h = bunpack(yu.x), a1h = bunpack(yu.y);
            float2 a0l = bunpack(yu.z), a1l = bunpack(yu.w);
            float y00 = a0h.x + a0l.x, y01 = a0h.y + a0l.y;
            float y10 = a1h.x + a1l.x, y11 = a1h.y + a1l.y;
            float g00 = acc[mi][ni][0], g01 = acc[mi][ni][1];
            float g10 = acc[mi][ni][2], g11 = acc[mi][ni][3];
            int gi0 = row0*DIM + col, gi1 = gi0 + 8*DIM;
            float2 b0 = *(const float2*)(g_b + gi0);
            float2 b1 = *(const float2*)(g_b + gi1);
            float fn00 = fmaxf(g00 + b0.x, 0.f), fn01 = fmaxf(g01 + b0.y, 0.f);
            float fn10 = fmaxf(g10 + b1.x, 0.f), fn11 = fmaxf(g11 + b1.y, 0.f);
            float d0 = y00-fn00, d1 = y01-fn01, d2 = y10-fn10, d3 = y11-fn11;
            sn = fmaf(d0,d0,sn); sn = fmaf(d1,d1,sn);
            sn = fmaf(d2,d2,sn); sn = fmaf(d3,d3,sn);
            sd = fmaf(y00,y00,sd); sd = fmaf(y01,y01,sd);
            sd = fmaf(y10,y10,sd); sd = fmaf(y11,y11,sd);
            *(float2*)(outp + gi0) = make_float2(fn00, fn01);
            *(float2*)(outp + gi1) = make_float2(fn10, fn11);
            float xn00 = fmaxf(0.5f*(y00 + g00 + b0.x), 0.f);
            float xn01 = fmaxf(0.5f*(y01 + g01 + b0.y), 0.f);
            float xn10 = fmaxf(0.5f*(y10 + g10 + b1.x), 0.f);
            float xn11 = fmaxf(0.5f*(y11 + g11 + b1.y), 0.f);
            int xi0 = gi0 >> 1, xi1 = gi1 >> 1;
            uint2 xu0 = xs[xi0], xu1 = xs[xi1];
            float2 x0h = bunpack(xu0.x), x0l = bunpack(xu0.y);
            float2 x1h = bunpack(xu1.x), x1l = bunpack(xu1.y);
            float yn00 = xn00 + beta*(xn00 - (x0h.x + x0l.x));
            float yn01 = xn01 + beta*(xn01 - (x0h.y + x0l.y));
            float yn10 = xn10 + beta*(xn10 - (x1h.x + x1l.x));
            float yn11 = xn11 + beta*(xn11 - (x1h.y + x1l.y));
            float r0, r1, r2, r3;
            uint32_t xh0 = split_hi(xn00, xn01, r0, r1);
            xsw[xi0] = make_uint2(xh0, pack_lo(r0, r1));
            uint32_t xh1 = split_hi(xn10, xn11, r2, r3);
            xsw[xi1] = make_uint2(xh1, pack_lo(r2, r3));
            uint32_t yh0 = split_hi(yn00, yn01, r0, r1);
            uint32_t yh1 = split_hi(yn10, yn11, r2, r3);
            yfw[yidx] = make_uint4(yh0, yh1, pack_lo(r0, r1), pack_lo(r2, r3));
        }
    }

    // ---- deterministic block reduction (reuse smem after sync) ----
    __syncthreads();
    float* red = (float*)ws;
    red[tid] = sn;  red[256 + tid] = sd;
    __syncthreads();
#pragma unroll
    for (int s = 128; s > 0; s >>= 1) {
        if (tid < s) { red[tid] += red[tid + s]; red[256 + tid] += red[256 + tid + s]; }
        __syncthreads();
    }
    const int cta = mb*4 + nb;
    if (tid == 0) {
        g_partial[cta*2    ] = red[0];
        g_partial[cta*2 + 1] = red[256];
    }

    // ---- merged convergence check: last CTA reduces and gates ----
    __shared__ int islast;
    __threadfence();
    if (tid == 0) islast = (atomicAdd(&g_ctr[it], 1) == NCTAS - 1);
    __syncthreads();
    if (islast) {
        float a = 0.f, b = 0.f;
#pragma unroll
        for (int k = 0; k < 4; ++k) {
            a += g_partial[2*(tid + k*256)    ];
            b += g_partial[2*(tid + k*256) + 1];
        }
        red[tid] = a; red[256 + tid] = b;
        __syncthreads();
#pragma unroll
        for (int s = 128; s > 0; s >>= 1) {
            if (tid < s) { red[tid] += red[tid + s]; red[256 + tid] += red[256 + tid + s]; }
            __syncthreads();
        }
        if (tid == 0) {
            float err = sqrtf(red[0]) / (1e-6f + sqrtf(red[256]));
            if (!(err > 1e-4f)) g_active = 0;
        }
    }
}

// ---------------- launch ----------------
extern "C" void kernel_launch(void* const* d_in, const int* in_sizes, int n_in,
                              void* d_out, int out_size) {
    const float* x  = (const float*)d_in[0];
    const float* U  = (const float*)d_in[1];
    const float* ub = (const float*)d_in[2];
    const float* A  = (const float*)d_in[3];
    const float* B  = (const float*)d_in[4];
    (void)in_sizes; (void)n_in; (void)out_size;

    static int attr_done = 0;
    if (!attr_done) {
        cudaFuncSetAttribute(iter_kernel,
                             cudaFuncAttributeMaxDynamicSharedMemorySize, WS_BYTES);
        attr_done = 1;
    }

    prep_kernel<<<DIM, DIM>>>(U, A, B);
    dim3 p2grid(16, 32);
    prep2_kernel<<<p2grid, 32>>>();
    init_kernel<<<YF_ELEMS/256, 256>>>();

    dim3 bgrid(2, 256);
    bias_gemm<<<bgrid, 256>>>(x, ub);

    dim3 igrid(4, 256);
    float t = 1.0f;
    for (int i = 1; i <= MAX_IT + 1; ++i) {
        float tn   = 0.5f * (1.0f + sqrtf(1.0f + 4.0f * t * t));
        float beta = (t - 1.0f) / tn;
        iter_kernel<<<igrid, 256, WS_BYTES>>>(beta, (i - 1) & 1, i - 1, (float*)d_out);
        t = tn;
    }
}

// round 11
// speedup vs baseline: 1.3404x; 1.1216x over previous
#include <cuda_runtime.h>
#include <cuda_bf16.h>
#include <math.h>
#include <stdint.h>

#define BATCH    32768
#define DIM      256
#define MAX_IT   40
#define NCTAS    1024              // grid (4, 256)
#define EW_GRID  (BATCH*DIM/4/256)
#define YF_ELEMS (2048*16*2*32)    // [mtile][kk16][half][lane] uint4
#define XS_ELEMS (BATCH*128)       // [row*128 + col/2] uint2
#define WS_BYTES 65536             // 4096 uint4: [kk][n8l][lane]

// ---------------- device scratch ----------------
__device__ uint4 g_yf[2][YF_ELEMS];     // y as A-fragments (hi,hi,lo,lo), ping-pong
__device__ uint2 g_xs[2][XS_ELEMS];     // x as interleaved bf16 splits, ping-pong
__device__ uint4 g_wf[16*32*32];        // W as B-fragments [kk][n8][lane]
__device__ float g_b[BATCH*DIM];
__device__ float g_WU[DIM*DIM];         // U^T for bias GEMM
__device__ __nv_bfloat16 g_w0[DIM*DIM]; // Weff hi split [k][n] (prep staging)
__device__ __nv_bfloat16 g_w1[DIM*DIM]; // Weff lo split
__device__ float g_partial[NCTAS*2];
__device__ int   g_ctr[MAX_IT+2];
__device__ int   g_active;
__device__ int   g_zpar;                // buffer index of final z (= y at exit)

// ---------------- helpers ----------------
__device__ __forceinline__ uint32_t bpack(__nv_bfloat16 a, __nv_bfloat16 b) {
    uint16_t ua = *(uint16_t*)&a, ub = *(uint16_t*)&b;
    return (uint32_t)ua | ((uint32_t)ub << 16);
}
__device__ __forceinline__ float2 bunpack(uint32_t u) {
    __nv_bfloat162 h = *(__nv_bfloat162*)&u;
    return make_float2(__bfloat162float(h.x), __bfloat162float(h.y));
}
__device__ __forceinline__ uint32_t split_hi(float a, float b,
                                             float& ra, float& rb) {
    __nv_bfloat16 ha = __float2bfloat16(a), hb = __float2bfloat16(b);
    ra = a - __bfloat162float(ha);
    rb = b - __bfloat162float(hb);
    return bpack(ha, hb);
}
__device__ __forceinline__ uint32_t pack_lo(float ra, float rb) {
    return bpack(__float2bfloat16(ra), __float2bfloat16(rb));
}
__device__ __forceinline__ void mma_bf16(float* c, const uint32_t* a, const uint32_t* b) {
    asm volatile(
        "mma.sync.aligned.m16n8k16.row.col.f32.bf16.bf16.f32 "
        "{%0,%1,%2,%3}, {%4,%5,%6,%7}, {%8,%9}, {%0,%1,%2,%3};"
        : "+f"(c[0]), "+f"(c[1]), "+f"(c[2]), "+f"(c[3])
        : "r"(a[0]), "r"(a[1]), "r"(a[2]), "r"(a[3]), "r"(b[0]), "r"(b[1]));
}

// fp32x2 helpers for the bias GEMM
__device__ __forceinline__ unsigned long long pack2(float v) {
    unsigned long long r; unsigned u = __float_as_uint(v);
    asm("mov.b64 %0, {%1, %1};" : "=l"(r) : "r"(u));
    return r;
}
__device__ __forceinline__ void ffma2(unsigned long long& d,
                                      unsigned long long a, unsigned long long b) {
    asm("fma.rn.f32x2 %0, %1, %2, %0;" : "+l"(d) : "l"(a), "l"(b));
}
__device__ __forceinline__ float lo32(unsigned long long v) {
    return __uint_as_float((unsigned)(v & 0xffffffffull));
}
__device__ __forceinline__ float hi32(unsigned long long v) {
    return __uint_as_float((unsigned)(v >> 32));
}

// ---------------- prep: U^T, Weff -> bf16 splits (row-major staging) ----------
__global__ void prep_kernel(const float* __restrict__ U,
                            const float* __restrict__ A,
                            const float* __restrict__ B) {
    int i = blockIdx.x;    // k
    int j = threadIdx.x;   // n
    g_WU[i*DIM + j] = U[j*DIM + i];
    float s = 0.f;
#pragma unroll 8
    for (int p = 0; p < DIM; ++p)
        s = fmaf(A[p*DIM + i], A[p*DIM + j], s);
    float w = -s + B[j*DIM + i] - B[i*DIM + j];
    if (i == j) w += 0.8f;                    // (1-m), m=0.2
    __nv_bfloat16 h0 = __float2bfloat16(w);
    __nv_bfloat16 h1 = __float2bfloat16(w - __bfloat162float(h0));
    g_w0[i*DIM + j] = h0;
    g_w1[i*DIM + j] = h1;
}

// ---------------- prep2: pack W into B-fragment order ----------------
// B frag m16n8k16 (col): lane T: b0={B[k0][n],B[k0+1][n]}, b1={B[k0+8][n],B[k0+9][n]}
// with k0 = kk*16 + 2*(T%4), n = n8*8 + T/4.
__global__ void prep2_kernel() {
    int kk = blockIdx.x, n8 = blockIdx.y, lane = threadIdx.x;
    int k0 = kk*16 + 2*(lane & 3);
    int n  = n8*8 + (lane >> 2);
    uint4 u;
    u.x = bpack(g_w0[(k0    )*DIM + n], g_w0[(k0+1)*DIM + n]);
    u.y = bpack(g_w0[(k0 + 8)*DIM + n], g_w0[(k0+9)*DIM + n]);
    u.z = bpack(g_w1[(k0    )*DIM + n], g_w1[(k0+1)*DIM + n]);
    u.w = bpack(g_w1[(k0 + 8)*DIM + n], g_w1[(k0+9)*DIM + n]);
    g_wf[(kk*32 + n8)*32 + lane] = u;
}

// ---------------- init: zero y frags, x splits, counters ----------------
__global__ void init_kernel() {
    int i = blockIdx.x * blockDim.x + threadIdx.x;   // 0..2M-1
    g_yf[0][i] = make_uint4(0u, 0u, 0u, 0u);
    g_xs[0][2*i    ] = make_uint2(0u, 0u);
    g_xs[0][2*i + 1] = make_uint2(0u, 0u);
    if (i == 0) { g_active = 1; g_zpar = 0; }
    if (i <= MAX_IT + 1) g_ctr[i] = 0;
}

// ---------------- bias GEMM (runs once, exact fp32): b = x @ U^T + ub ----------
__launch_bounds__(256, 2)
__global__ void bias_gemm(const float* __restrict__ Ap, const float* __restrict__ ub) {
    __shared__ float As[16][132];
    __shared__ float Bs[16][128];
    const int tid = threadIdx.x;
    const int tx  = tid & 15, ty = tid >> 4;
    const int m0  = blockIdx.y * 128, n0 = blockIdx.x * 128;
    const int ra = tid >> 2, ca = (tid & 3) << 2;
    const int rb = tid >> 5, cb = (tid & 31) << 2;
    unsigned long long acc[8][4];
#pragma unroll
    for (int i = 0; i < 8; ++i)
#pragma unroll
        for (int j = 0; j < 4; ++j) acc[i][j] = 0ull;
    for (int k0 = 0; k0 < DIM; k0 += 16) {
        float4 a0 = *(const float4*)(Ap + (m0 + ra     ) * DIM + k0 + ca);
        float4 a1 = *(const float4*)(Ap + (m0 + ra + 64) * DIM + k0 + ca);
        float4 b0 = *(const float4*)(g_WU + (k0 + rb    ) * DIM + n0 + cb);
        float4 b1 = *(const float4*)(g_WU + (k0 + rb + 8) * DIM + n0 + cb);
        __syncthreads();
        As[ca+0][ra] = a0.x;  As[ca+1][ra] = a0.y;
        As[ca+2][ra] = a0.z;  As[ca+3][ra] = a0.w;
        As[ca+0][ra+64] = a1.x;  As[ca+1][ra+64] = a1.y;
        As[ca+2][ra+64] = a1.z;  As[ca+3][ra+64] = a1.w;
        *(float4*)&Bs[rb  ][cb] = b0;
        *(float4*)&Bs[rb+8][cb] = b1;
        __syncthreads();
#pragma unroll
        for (int kk = 0; kk < 16; ++kk) {
            unsigned long long pb[4], pa[8];
#pragma unroll
            for (int j = 0; j < 4; ++j)
                pb[j] = *(const unsigned long long*)&Bs[kk][tx*2 + j*32];
#pragma unroll
            for (int i = 0; i < 8; ++i) pa[i] = pack2(As[kk][ty*8 + i]);
#pragma unroll
            for (int i = 0; i < 8; ++i)
#pragma unroll
                for (int j = 0; j < 4; ++j) ffma2(acc[i][j], pa[i], pb[j]);
        }
    }
    float2 u[4];
#pragma unroll
    for (int j = 0; j < 4; ++j) u[j] = *(const float2*)(ub + n0 + tx*2 + j*32);
#pragma unroll
    for (int i = 0; i < 8; ++i) {
        float* base = g_b + (m0 + ty*8 + i)*DIM + n0;
#pragma unroll
        for (int j = 0; j < 4; ++j) {
            float2 g;
            g.x = lo32(acc[i][j]) + u[j].x;
            g.y = hi32(acc[i][j]) + u[j].y;
            *(float2*)(base + tx*2 + j*32) = g;
        }
    }
}

// ---------------- iteration kernel (no output stores) ----------
// CTA tile 128M x 64N; 8 warps (4 M x 2 N), warp tile 32x32.
// G = a0@w0 + a1@w0 + a0@w1; epilogue: err partials (fn in regs only),
// x' = relu(0.5*(y+G+b)); y' = x' + beta*(x'-x); merged last-CTA check.
__global__ void __launch_bounds__(256, 3)
iter_kernel(float beta, int par, int it) {
    if (g_active == 0) return;
    extern __shared__ __align__(16) uint4 ws[];   // [kk][n8l][lane] = 4096 uint4
    const int tid  = threadIdx.x;
    const int lane = tid & 31;
    const int wid  = tid >> 5;
    const int wm   = wid & 3;          // M slice (32 rows)
    const int wn   = wid >> 2;         // N slice (32 cols)
    const int mb   = blockIdx.y;       // 0..255
    const int nb   = blockIdx.x;       // 0..3

    // ---- stage this CTA's W-fragment slice (64 cols) into smem ----
#pragma unroll
    for (int j = 0; j < 16; ++j) {
        int linear = j*256 + tid;              // (kk*8 + n8l)*32 + lane
        int l  = linear & 31;
        int r  = linear >> 5;                  // 0..127
        int kk = r >> 3, n8l = r & 7;
        ws[linear] = g_wf[kk*1024 + (nb*8 + n8l)*32 + l];
    }
    __syncthreads();

    const uint4* __restrict__ yf = g_yf[par];

    float acc[2][4][4];
#pragma unroll
    for (int mi = 0; mi < 2; ++mi)
#pragma unroll
        for (int ni = 0; ni < 4; ++ni)
#pragma unroll
            for (int q = 0; q < 4; ++q) acc[mi][ni][q] = 0.f;

    const int mt0 = mb*8 + wm*2;

#pragma unroll
    for (int kk = 0; kk < 16; ++kk) {
        uint32_t ah[2][4], al[2][4];
#pragma unroll
        for (int mi = 0; mi < 2; ++mi) {
            int base = (((mt0 + mi)*16 + kk)*2)*32 + lane;
            uint4 u0 = yf[base];
            uint4 u1 = yf[base + 32];
            ah[mi][0] = u0.x; ah[mi][1] = u0.y; ah[mi][2] = u1.x; ah[mi][3] = u1.y;
            al[mi][0] = u0.z; al[mi][1] = u0.w; al[mi][2] = u1.z; al[mi][3] = u1.w;
        }
#pragma unroll
        for (int ni = 0; ni < 4; ++ni) {
            uint4 u = ws[(kk*8 + wn*4 + ni)*32 + lane];
            uint32_t bh[2] = {u.x, u.y};
            uint32_t bl[2] = {u.z, u.w};
#pragma unroll
            for (int mi = 0; mi < 2; ++mi) {
                float* c = acc[mi][ni];
                mma_bf16(c, ah[mi], bh);
                mma_bf16(c, al[mi], bh);
                mma_bf16(c, ah[mi], bl);
            }
        }
    }

    // ---- fused epilogue (no out stores) ----
    const uint2* __restrict__ xs = g_xs[par];
    uint2* __restrict__ xsw = g_xs[par ^ 1];
    uint4* __restrict__ yfw = g_yf[par ^ 1];
    const int t2 = lane & 3, g = lane >> 2;
    float sn = 0.f, sd = 0.f;

#pragma unroll
    for (int mi = 0; mi < 2; ++mi) {
        int row0 = mb*128 + wm*32 + mi*16 + g;
#pragma unroll
        for (int ni = 0; ni < 4; ++ni) {
            int k8  = nb*8 + wn*4 + ni;
            int col = k8*8 + t2*2;
            int yidx = (((mt0 + mi)*16 + (k8 >> 1))*2 + (k8 & 1))*32 + lane;
            uint4 yu = yf[yidx];
            float2 a0h = bunpack(yu.x), a1h = bunpack(yu.y);
            float2 a0l = bunpack(yu.z), a1l = bunpack(yu.w);
            float y00 = a0h.x + a0l.x, y01 = a0h.y + a0l.y;
            float y10 = a1h.x + a1l.x, y11 = a1h.y + a1l.y;
            float g00 = acc[mi][ni][0], g01 = acc[mi][ni][1];
            float g10 = acc[mi][ni][2], g11 = acc[mi][ni][3];
            int gi0 = row0*DIM + col, gi1 = gi0 + 8*DIM;
            float2 b0 = *(const float2*)(g_b + gi0);
            float2 b1 = *(const float2*)(g_b + gi1);
            float fn00 = fmaxf(g00 + b0.x, 0.f), fn01 = fmaxf(g01 + b0.y, 0.f);
            float fn10 = fmaxf(g10 + b1.x, 0.f), fn11 = fmaxf(g11 + b1.y, 0.f);
            float d0 = y00-fn00, d1 = y01-fn01, d2 = y10-fn10, d3 = y11-fn11;
            sn = fmaf(d0,d0,sn); sn = fmaf(d1,d1,sn);
            sn = fmaf(d2,d2,sn); sn = fmaf(d3,d3,sn);
            sd = fmaf(y00,y00,sd); sd = fmaf(y01,y01,sd);
            sd = fmaf(y10,y10,sd); sd = fmaf(y11,y11,sd);
            float xn00 = fmaxf(0.5f*(y00 + g00 + b0.x), 0.f);
            float xn01 = fmaxf(0.5f*(y01 + g01 + b0.y), 0.f);
            float xn10 = fmaxf(0.5f*(y10 + g10 + b1.x), 0.f);
            float xn11 = fmaxf(0.5f*(y11 + g11 + b1.y), 0.f);
            int xi0 = gi0 >> 1, xi1 = gi1 >> 1;
            uint2 xu0 = xs[xi0], xu1 = xs[xi1];
            float2 x0h = bunpack(xu0.x), x0l = bunpack(xu0.y);
            float2 x1h = bunpack(xu1.x), x1l = bunpack(xu1.y);
            float yn00 = xn00 + beta*(xn00 - (x0h.x + x0l.x));
            float yn01 = xn01 + beta*(xn01 - (x0h.y + x0l.y));
            float yn10 = xn10 + beta*(xn10 - (x1h.x + x1l.x));
            float yn11 = xn11 + beta*(xn11 - (x1h.y + x1l.y));
            float r0, r1, r2, r3;
            uint32_t xh0 = split_hi(xn00, xn01, r0, r1);
            xsw[xi0] = make_uint2(xh0, pack_lo(r0, r1));
            uint32_t xh1 = split_hi(xn10, xn11, r2, r3);
            xsw[xi1] = make_uint2(xh1, pack_lo(r2, r3));
            uint32_t yh0 = split_hi(yn00, yn01, r0, r1);
            uint32_t yh1 = split_hi(yn10, yn11, r2, r3);
            yfw[yidx] = make_uint4(yh0, yh1, pack_lo(r0, r1), pack_lo(r2, r3));
        }
    }

    // ---- deterministic block reduction (reuse smem after sync) ----
    __syncthreads();
    float* red = (float*)ws;
    red[tid] = sn;  red[256 + tid] = sd;
    __syncthreads();
#pragma unroll
    for (int s = 128; s > 0; s >>= 1) {
        if (tid < s) { red[tid] += red[tid + s]; red[256 + tid] += red[256 + tid + s]; }
        __syncthreads();
    }
    const int cta = mb*4 + nb;
    if (tid == 0) {
        g_partial[cta*2    ] = red[0];
        g_partial[cta*2 + 1] = red[256];
    }

    // ---- merged convergence check: last CTA reduces and gates ----
    __shared__ int islast;
    __threadfence();
    if (tid == 0) islast = (atomicAdd(&g_ctr[it], 1) == NCTAS - 1);
    __syncthreads();
    if (islast) {
        float a = 0.f, b = 0.f;
#pragma unroll
        for (int k = 0; k < 4; ++k) {
            a += g_partial[2*(tid + k*256)    ];
            b += g_partial[2*(tid + k*256) + 1];
        }
        red[tid] = a; red[256 + tid] = b;
        __syncthreads();
#pragma unroll
        for (int s = 128; s > 0; s >>= 1) {
            if (tid < s) { red[tid] += red[tid + s]; red[256 + tid] += red[256 + tid + s]; }
            __syncthreads();
        }
        if (tid == 0) {
            float err = sqrtf(red[0]) / (1e-6f + sqrtf(red[256]));
            if (!(err > 1e-4f)) {
                g_active = 0;
                g_zpar = par;      // z = y of body (it) lives in buffer `par`
            }
        }
    }
}

// ---------------- final kernel: out = relu(z @ W + b), z = g_yf[g_zpar] ------
__global__ void __launch_bounds__(256, 3)
final_kernel(float* __restrict__ outp) {
    extern __shared__ __align__(16) uint4 ws[];
    const int tid  = threadIdx.x;
    const int lane = tid & 31;
    const int wid  = tid >> 5;
    const int wm   = wid & 3;
    const int wn   = wid >> 2;
    const int mb   = blockIdx.y;
    const int nb   = blockIdx.x;
    const int par  = g_zpar;

#pragma unroll
    for (int j = 0; j < 16; ++j) {
        int linear = j*256 + tid;
        int l  = linear & 31;
        int r  = linear >> 5;
        int kk = r >> 3, n8l = r & 7;
        ws[linear] = g_wf[kk*1024 + (nb*8 + n8l)*32 + l];
    }
    __syncthreads();

    const uint4* __restrict__ yf = g_yf[par];

    float acc[2][4][4];
#pragma unroll
    for (int mi = 0; mi < 2; ++mi)
#pragma unroll
        for (int ni = 0; ni < 4; ++ni)
#pragma unroll
            for (int q = 0; q < 4; ++q) acc[mi][ni][q] = 0.f;

    const int mt0 = mb*8 + wm*2;

#pragma unroll
    for (int kk = 0; kk < 16; ++kk) {
        uint32_t ah[2][4], al[2][4];
#pragma unroll
        for (int mi = 0; mi < 2; ++mi) {
            int base = (((mt0 + mi)*16 + kk)*2)*32 + lane;
            uint4 u0 = yf[base];
            uint4 u1 = yf[base + 32];
            ah[mi][0] = u0.x; ah[mi][1] = u0.y; ah[mi][2] = u1.x; ah[mi][3] = u1.y;
            al[mi][0] = u0.z; al[mi][1] = u0.w; al[mi][2] = u1.z; al[mi][3] = u1.w;
        }
#pragma unroll
        for (int ni = 0; ni < 4; ++ni) {
            uint4 u = ws[(kk*8 + wn*4 + ni)*32 + lane];
            uint32_t bh[2] = {u.x, u.y};
            uint32_t bl[2] = {u.z, u.w};
#pragma unroll
            for (int mi = 0; mi < 2; ++mi) {
                float* c = acc[mi][ni];
                mma_bf16(c, ah[mi], bh);
                mma_bf16(c, al[mi], bh);
                mma_bf16(c, ah[mi], bl);
            }
        }
    }

    const int t2 = lane & 3, g = lane >> 2;
#pragma unroll
    for (int mi = 0; mi < 2; ++mi) {
        int row0 = mb*128 + wm*32 + mi*16 + g;
#pragma unroll
        for (int ni = 0; ni < 4; ++ni) {
            int k8  = nb*8 + wn*4 + ni;
            int col = k8*8 + t2*2;
            int gi0 = row0*DIM + col, gi1 = gi0 + 8*DIM;
            float2 b0 = *(const float2*)(g_b + gi0);
            float2 b1 = *(const float2*)(g_b + gi1);
            *(float2*)(outp + gi0) = make_float2(
                fmaxf(acc[mi][ni][0] + b0.x, 0.f),
                fmaxf(acc[mi][ni][1] + b0.y, 0.f));
            *(float2*)(outp + gi1) = make_float2(
                fmaxf(acc[mi][ni][2] + b1.x, 0.f),
                fmaxf(acc[mi][ni][3] + b1.y, 0.f));
        }
    }
}

// ---------------- launch ----------------
extern "C" void kernel_launch(void* const* d_in, const int* in_sizes, int n_in,
                              void* d_out, int out_size) {
    const float* x  = (const float*)d_in[0];
    const float* U  = (const float*)d_in[1];
    const float* ub = (const float*)d_in[2];
    const float* A  = (const float*)d_in[3];
    const float* B  = (const float*)d_in[4];
    (void)in_sizes; (void)n_in; (void)out_size;

    static int attr_done = 0;
    if (!attr_done) {
        cudaFuncSetAttribute(iter_kernel,
                             cudaFuncAttributeMaxDynamicSharedMemorySize, WS_BYTES);
        cudaFuncSetAttribute(final_kernel,
                             cudaFuncAttributeMaxDynamicSharedMemorySize, WS_BYTES);
        attr_done = 1;
    }

    prep_kernel<<<DIM, DIM>>>(U, A, B);
    dim3 p2grid(16, 32);
    prep2_kernel<<<p2grid, 32>>>();
    init_kernel<<<YF_ELEMS/256, 256>>>();

    dim3 bgrid(2, 256);
    bias_gemm<<<bgrid, 256>>>(x, ub);

    dim3 igrid(4, 256);
    float t = 1.0f;
    for (int i = 1; i <= MAX_IT; ++i) {
        float tn   = 0.5f * (1.0f + sqrtf(1.0f + 4.0f * t * t));
        float beta = (t - 1.0f) / tn;
        iter_kernel<<<igrid, 256, WS_BYTES>>>(beta, (i - 1) & 1, i - 1);
        t = tn;
    }
    final_kernel<<<igrid, 256, WS_BYTES>>>((float*)d_out);
}